// round 1
// baseline (speedup 1.0000x reference)
#include <cuda_runtime.h>

// Problem constants (match reference)
#define B  16
#define LX 2048
#define LR 1024
#define D  768
#define T  (LX + LR + 3)   // 3075
#define D4 (D / 4)         // 192 float4 per row

// out[b,t,:] =
//   t == 0                          : CLS
//   1 <= t <= lx[b]                 : X[b, t-1]
//   t == lx[b]+1                    : RING
//   lx[b]+2 <= t < lx[b]+2+lr[b]    : Xr[b, t-lx[b]-2]
//   t == lx[b]+lr[b]+2              : END
//   else                            : 0
__global__ __launch_bounds__(D4) void assemble_kernel(
    const float4* __restrict__ X,
    const float4* __restrict__ Xr,
    const float4* __restrict__ CLS,
    const float4* __restrict__ RING,
    const float4* __restrict__ END,
    const int*    __restrict__ lx,
    const int*    __restrict__ lr,
    float4*       __restrict__ out)
{
    const int row = blockIdx.x;       // b * T + t
    const int b   = row / T;
    const int t   = row - b * T;
    const int c   = threadIdx.x;      // 0..191

    const int lxb = __ldg(&lx[b]);
    const int lrb = __ldg(&lr[b]);

    float4 v;
    if (t == 0) {
        v = CLS[c];
    } else if (t <= lxb) {
        v = X[((long)b * LX + (t - 1)) * D4 + c];
    } else if (t == lxb + 1) {
        v = RING[c];
    } else if (t < lxb + 2 + lrb) {
        v = Xr[((long)b * LR + (t - lxb - 2)) * D4 + c];
    } else if (t == lxb + lrb + 2) {
        v = END[c];
    } else {
        v = make_float4(0.f, 0.f, 0.f, 0.f);
    }

    out[(long)row * D4 + c] = v;
}

extern "C" void kernel_launch(void* const* d_in, const int* in_sizes, int n_in,
                              void* d_out, int out_size)
{
    const float4* X    = (const float4*)d_in[0];
    const float4* Xr   = (const float4*)d_in[1];
    const float4* CLS  = (const float4*)d_in[2];
    const float4* RING = (const float4*)d_in[3];
    const float4* END  = (const float4*)d_in[4];
    const int*    lx   = (const int*)d_in[5];
    const int*    lr   = (const int*)d_in[6];
    float4*       out  = (float4*)d_out;

    dim3 grid(B * T);
    dim3 block(D4);
    assemble_kernel<<<grid, block>>>(X, Xr, CLS, RING, END, lx, lr, out);
}

// round 2
// speedup vs baseline: 1.0073x; 1.0073x over previous
#include <cuda_runtime.h>

// Problem constants (match reference)
#define B   16
#define LX  2048
#define LR  1024
#define D   768
#define T   (LX + LR + 3)   // 3075
#define D4  (D / 4)         // 192 float4 per row
#define RPB 4               // rows per CTA (B*T = 49200 divisible by 4)

// out[b,t,:] =
//   t == 0                          : CLS
//   1 <= t <= lx[b]                 : X[b, t-1]
//   t == lx[b]+1                    : RING
//   lx[b]+2 <= t < lx[b]+2+lr[b]    : Xr[b, t-lx[b]-2]
//   t == lx[b]+lr[b]+2              : END
//   else                            : 0
__global__ __launch_bounds__(D4) void assemble_kernel(
    const float4* __restrict__ X,
    const float4* __restrict__ Xr,
    const float4* __restrict__ CLS,
    const float4* __restrict__ RING,
    const float4* __restrict__ END,
    const int*    __restrict__ lx,
    const int*    __restrict__ lr,
    float4*       __restrict__ out)
{
    const int c    = threadIdx.x;            // 0..191
    const int row0 = blockIdx.x * RPB;       // first of RPB consecutive rows

    float4 v[RPB];

    #pragma unroll
    for (int i = 0; i < RPB; i++) {
        const int row = row0 + i;
        const int b   = row / T;              // const-div -> mul/shift
        const int t   = row - b * T;

        const int lxb = __ldg(&lx[b]);
        const int lrb = __ldg(&lr[b]);

        if (t == 0) {
            v[i] = CLS[c];
        } else if (t <= lxb) {
            v[i] = __ldcs(&X[((long)b * LX + (t - 1)) * D4 + c]);
        } else if (t == lxb + 1) {
            v[i] = RING[c];
        } else if (t < lxb + 2 + lrb) {
            v[i] = __ldcs(&Xr[((long)b * LR + (t - lxb - 2)) * D4 + c]);
        } else if (t == lxb + lrb + 2) {
            v[i] = END[c];
        } else {
            v[i] = make_float4(0.f, 0.f, 0.f, 0.f);
        }
    }

    #pragma unroll
    for (int i = 0; i < RPB; i++) {
        __stcs(&out[(long)(row0 + i) * D4 + c], v[i]);
    }
}

extern "C" void kernel_launch(void* const* d_in, const int* in_sizes, int n_in,
                              void* d_out, int out_size)
{
    const float4* X    = (const float4*)d_in[0];
    const float4* Xr   = (const float4*)d_in[1];
    const float4* CLS  = (const float4*)d_in[2];
    const float4* RING = (const float4*)d_in[3];
    const float4* END  = (const float4*)d_in[4];
    const int*    lx   = (const int*)d_in[5];
    const int*    lr   = (const int*)d_in[6];
    float4*       out  = (float4*)d_out;

    dim3 grid((B * T) / RPB);   // 12300 CTAs
    dim3 block(D4);             // 192 threads
    assemble_kernel<<<grid, block>>>(X, Xr, CLS, RING, END, lx, lr, out);
}